// round 1
// baseline (speedup 1.0000x reference)
#include <cuda_runtime.h>
#include <cuda_bf16.h>
#include <cstdint>

// ---------------- Problem constants ----------------
static constexpr int MAXN = 100000;
static constexpr int MAXE = 3200000;
static constexpr int HID  = 256;
static constexpr int OUTD = 64;

// ---------------- Device scratch (no allocations allowed) ----------------
__device__ int   g_deg[MAXN];
__device__ float g_dinv[MAXN];
__device__ int   g_rowptr[MAXN + 1];
__device__ int   g_ctr[MAXN];
__device__ int   g_bsums[1024];
__device__ int   g_nonzero;
__device__ int   g_col[MAXE + MAXN];
__device__ float g_val[MAXE + MAXN];
__device__ float g_h1[(size_t)MAXN * HID];   // MLP hidden
__device__ float g_h0[(size_t)MAXN * OUTD];  // teleport anchor
__device__ float g_ha[(size_t)MAXN * OUTD];  // ping
__device__ float g_hb[(size_t)MAXN * OUTD];  // pong

// ---------------- edge index access (int64 vs int32 detected at runtime) ----
__device__ __forceinline__ int edge_at(const void* p, int is64, long long i) {
    return is64 ? (int)((const long long*)p)[i] : ((const int*)p)[i];
}

__global__ void k_init(int n) {
    int i = blockIdx.x * blockDim.x + threadIdx.x;
    if (i < n) g_deg[i] = 1;              // self-loop contributes 1 to every degree
    if (i == 0) g_nonzero = 0;
}

// If buffer is int64 (values < 1e5), every odd 32-bit word is 0.
__global__ void k_detect(const int* p) {
    int v = p[2 * threadIdx.x + 1];
    if (v != 0) atomicOr(&g_nonzero, 1);
}

__global__ void k_count(const void* e, int E) {
    int i = blockIdx.x * blockDim.x + threadIdx.x;
    if (i >= E) return;
    int is64 = (g_nonzero == 0);
    int d = edge_at(e, is64, (long long)E + i);
    atomicAdd(&g_deg[d], 1);
}

__global__ void k_dinv(int n) {
    int i = blockIdx.x * blockDim.x + threadIdx.x;
    if (i < n) g_dinv[i] = rsqrtf((float)g_deg[i]);
}

// ---------------- 3-kernel exclusive scan of g_deg -> g_rowptr --------------
__global__ void k_scan1(int n) {
    __shared__ int ws[32];
    int b = blockIdx.x, t = threadIdx.x;
    int i = b * 1024 + t;
    int v = (i < n) ? g_deg[i] : 0;
    int lane = t & 31, wid = t >> 5;
    int x = v;
#pragma unroll
    for (int o = 1; o < 32; o <<= 1) { int y = __shfl_up_sync(0xffffffffu, x, o); if (lane >= o) x += y; }
    if (lane == 31) ws[wid] = x;
    __syncthreads();
    if (wid == 0) {
        int s = ws[lane];
#pragma unroll
        for (int o = 1; o < 32; o <<= 1) { int y = __shfl_up_sync(0xffffffffu, s, o); if (lane >= o) s += y; }
        ws[lane] = s;
    }
    __syncthreads();
    int off = wid ? ws[wid - 1] : 0;
    if (i < n) g_rowptr[i] = off + x - v;       // local exclusive
    if (t == 1023) g_bsums[b] = ws[31];         // block total
}

__global__ void k_scan2(int nb) {
    __shared__ int ws[32];
    int t = threadIdx.x;
    int v = (t < nb) ? g_bsums[t] : 0;
    int lane = t & 31, wid = t >> 5;
    int x = v;
#pragma unroll
    for (int o = 1; o < 32; o <<= 1) { int y = __shfl_up_sync(0xffffffffu, x, o); if (lane >= o) x += y; }
    if (lane == 31) ws[wid] = x;
    __syncthreads();
    if (wid == 0) {
        int s = ws[lane];
#pragma unroll
        for (int o = 1; o < 32; o <<= 1) { int y = __shfl_up_sync(0xffffffffu, s, o); if (lane >= o) s += y; }
        ws[lane] = s;
    }
    __syncthreads();
    int off = wid ? ws[wid - 1] : 0;
    if (t < nb) g_bsums[t] = off + x - v;       // exclusive, in place
}

__global__ void k_scan3(int n, int total) {
    int i = blockIdx.x * blockDim.x + threadIdx.x;
    if (i < n) {
        g_rowptr[i] += g_bsums[i >> 10];
        g_ctr[i] = g_rowptr[i];                 // init fill cursors
    }
    if (i == 0) g_rowptr[n] = total;
}

__global__ void k_fill(const void* e, int E, int n) {
    int i = blockIdx.x * blockDim.x + threadIdx.x;
    if (i >= E + n) return;
    int is64 = (g_nonzero == 0);
    int s, d;
    if (i < E) { s = edge_at(e, is64, i); d = edge_at(e, is64, (long long)E + i); }
    else       { s = d = i - E; }
    int p = atomicAdd(&g_ctr[d], 1);
    g_col[p] = s;
    g_val[p] = g_dinv[s] * g_dinv[d];
}

// ---------------- fp32 tiled GEMM: C = [relu](A*B + bias) -------------------
template <int BM, int BN, int BK, int TM, int TN, bool RELU>
__global__ void gemm_bias(const float* __restrict__ A, const float* __restrict__ B,
                          const float* __restrict__ bias, float* __restrict__ C,
                          int M, int N, int K) {
    constexpr int THREADS = (BM / TM) * (BN / TN);
    __shared__ float As[BK][BM + 1];
    __shared__ float Bs[BK][BN];
    int tid = threadIdx.x;
    int bm = blockIdx.x * BM;
    int bn = blockIdx.y * BN;
    int tcol = tid % (BN / TN);
    int trow = tid / (BN / TN);
    float acc[TM][TN] = {};

    constexpr int A_LD = BM * BK / (4 * THREADS);
    constexpr int B_LD = BK * BN / (4 * THREADS);

    for (int k0 = 0; k0 < K; k0 += BK) {
#pragma unroll
        for (int j = 0; j < A_LD; j++) {
            int lin = tid + j * THREADS;        // float4 index over [BM][BK/4]
            int r = lin / (BK / 4);
            int c4 = lin % (BK / 4);
            int grow = bm + r;
            float4 v = make_float4(0.f, 0.f, 0.f, 0.f);
            if (grow < M) v = *(const float4*)&A[(size_t)grow * K + k0 + c4 * 4];
            As[c4 * 4 + 0][r] = v.x;
            As[c4 * 4 + 1][r] = v.y;
            As[c4 * 4 + 2][r] = v.z;
            As[c4 * 4 + 3][r] = v.w;
        }
#pragma unroll
        for (int j = 0; j < B_LD; j++) {
            int lin = tid + j * THREADS;        // float4 index over [BK][BN/4]
            int r = lin / (BN / 4);
            int c4 = lin % (BN / 4);
            *(float4*)&Bs[r][c4 * 4] = *(const float4*)&B[(size_t)(k0 + r) * N + bn + c4 * 4];
        }
        __syncthreads();
#pragma unroll
        for (int kk = 0; kk < BK; kk++) {
            float ra[TM], rb[TN];
#pragma unroll
            for (int i = 0; i < TM; i++) ra[i] = As[kk][trow * TM + i];
#pragma unroll
            for (int j = 0; j < TN; j++) rb[j] = Bs[kk][tcol * TN + j];
#pragma unroll
            for (int i = 0; i < TM; i++)
#pragma unroll
                for (int j = 0; j < TN; j++)
                    acc[i][j] += ra[i] * rb[j];
        }
        __syncthreads();
    }
#pragma unroll
    for (int i = 0; i < TM; i++) {
        int grow = bm + trow * TM + i;
        if (grow >= M) continue;
#pragma unroll
        for (int j = 0; j < TN; j++) {
            int gcol = bn + tcol * TN + j;
            float v = acc[i][j] + bias[gcol];
            if (RELU) v = fmaxf(v, 0.f);
            C[(size_t)grow * N + gcol] = v;
        }
    }
}

// ---------------- propagation: one warp per destination row -----------------
__global__ void k_prop(const float* __restrict__ hin, const float* __restrict__ h0,
                       float* __restrict__ hout, int n) {
    int w = (blockIdx.x * blockDim.x + threadIdx.x) >> 5;
    if (w >= n) return;
    int lane = threadIdx.x & 31;
    int s = g_rowptr[w], e = g_rowptr[w + 1];
    float a0 = 0.f, a1 = 0.f;
    int i = s;
    for (; i + 1 < e; i += 2) {
        int   c0 = __ldg(&g_col[i]);     float w0 = __ldg(&g_val[i]);
        int   c1 = __ldg(&g_col[i + 1]); float w1 = __ldg(&g_val[i + 1]);
        float2 p0 = *(const float2*)(hin + (size_t)c0 * OUTD + lane * 2);
        float2 p1 = *(const float2*)(hin + (size_t)c1 * OUTD + lane * 2);
        a0 += w0 * p0.x + w1 * p1.x;
        a1 += w0 * p0.y + w1 * p1.y;
    }
    if (i < e) {
        int c = __ldg(&g_col[i]); float wv = __ldg(&g_val[i]);
        float2 p = *(const float2*)(hin + (size_t)c * OUTD + lane * 2);
        a0 += wv * p.x; a1 += wv * p.y;
    }
    size_t o = (size_t)w * OUTD + lane * 2;
    float2 z = *(const float2*)(h0 + o);
    float2 r;
    r.x = 0.9f * a0 + 0.1f * z.x;
    r.y = 0.9f * a1 + 0.1f * z.y;
    *(float2*)(hout + o) = r;
}

// ---------------- launch ----------------------------------------------------
extern "C" void kernel_launch(void* const* d_in, const int* in_sizes, int n_in,
                              void* d_out, int out_size) {
    const float* x  = (const float*)d_in[0];
    const void*  ei = d_in[1];
    const float* W1 = (const float*)d_in[2];
    const float* b1 = (const float*)d_in[3];
    const float* W2 = (const float*)d_in[4];
    const float* b2 = (const float*)d_in[5];
    float* out = (float*)d_out;

    int N = in_sizes[0] / 512;
    int E = in_sizes[1] / 2;

    void* p;
    cudaGetSymbolAddress(&p, g_h1); float* h1 = (float*)p;
    cudaGetSymbolAddress(&p, g_h0); float* h0 = (float*)p;
    cudaGetSymbolAddress(&p, g_ha); float* ha = (float*)p;
    cudaGetSymbolAddress(&p, g_hb); float* hb = (float*)p;

    int nb = (N + 1023) / 1024;

    // ---- CSR build ----
    k_init<<<(N + 255) / 256, 256>>>(N);
    k_detect<<<1, 1024>>>((const int*)ei);
    k_count<<<(E + 255) / 256, 256>>>(ei, E);
    k_dinv<<<(N + 255) / 256, 256>>>(N);
    k_scan1<<<nb, 1024>>>(N);
    k_scan2<<<1, 1024>>>(nb);
    k_scan3<<<nb, 1024>>>(N, E + N);
    k_fill<<<(E + N + 255) / 256, 256>>>(ei, E, N);

    // ---- MLP head: h0 = relu(x@W1+b1)@W2 + b2 ----
    dim3 g1((N + 127) / 128, HID / 64);
    gemm_bias<128, 64, 16, 8, 4, true><<<g1, 256>>>(x, W1, b1, h1, N, HID, 512);
    dim3 g2((N + 127) / 128, OUTD / 64);
    gemm_bias<128, 64, 16, 8, 4, false><<<g2, 256>>>(h1, W2, b2, h0, N, OUTD, HID);

    // ---- K=10 propagation rounds, ping-pong, last writes d_out ----
    float* bufs[3] = {h0, ha, hb};
    int cur = 0;
    int blocks = (N * 32 + 255) / 256;
    for (int it = 0; it < 10; it++) {
        float* hin = bufs[cur];
        float* hout;
        if (it == 9) {
            hout = out;
        } else {
            int nxt = (cur == 1) ? 2 : 1;
            hout = bufs[nxt];
            cur = nxt;
        }
        k_prop<<<blocks, 256>>>(hin, h0, hout, N);
    }
}

// round 3
// speedup vs baseline: 1.4012x; 1.4012x over previous
#include <cuda_runtime.h>
#include <cuda_bf16.h>
#include <cuda_fp16.h>
#include <cstdint>

// ---------------- Problem constants ----------------
static constexpr int MAXN = 100000;
static constexpr int MAXE = 3200000;
static constexpr int IND  = 512;
static constexpr int HID  = 256;
static constexpr int OUTD = 64;

// ---------------- Device scratch ----------------
__device__ int   g_deg[MAXN];
__device__ float g_dinv[MAXN];
__device__ int   g_rowptr[MAXN + 1];
__device__ int   g_ctr[MAXN];
__device__ int   g_bsums[1024];
__device__ int   g_nonzero;
__device__ int   g_col[MAXE + MAXN];
__device__ float g_val[MAXE + MAXN];
__device__ __nv_bfloat16 g_w1h[IND * HID], g_w1l[IND * HID];
__device__ __nv_bfloat16 g_w2h[HID * OUTD], g_w2l[HID * OUTD];
__device__ float  g_h1[(size_t)MAXN * HID];
__device__ float  g_h0[(size_t)MAXN * OUTD];
__device__ __half g_h16a[(size_t)MAXN * OUTD];
__device__ __half g_h16b[(size_t)MAXN * OUTD];

// ================= helpers =================
__device__ __forceinline__ uint32_t smem_u32(const void* p) {
    uint32_t a;
    asm("{ .reg .u64 t; cvta.to.shared.u64 t, %1; cvt.u32.u64 %0, t; }" : "=r"(a) : "l"(p));
    return a;
}
__device__ __forceinline__ void ldsm4(uint32_t* r, uint32_t a) {
    asm volatile("ldmatrix.sync.aligned.m8n8.x4.shared.b16 {%0,%1,%2,%3}, [%4];"
        : "=r"(r[0]), "=r"(r[1]), "=r"(r[2]), "=r"(r[3]) : "r"(a));
}
__device__ __forceinline__ void ldsm4t(uint32_t* r, uint32_t a) {
    asm volatile("ldmatrix.sync.aligned.m8n8.x4.trans.shared.b16 {%0,%1,%2,%3}, [%4];"
        : "=r"(r[0]), "=r"(r[1]), "=r"(r[2]), "=r"(r[3]) : "r"(a));
}
__device__ __forceinline__ void mma16816(float* d, const uint32_t* a, const uint32_t* b) {
    asm volatile("mma.sync.aligned.m16n8k16.row.col.f32.bf16.bf16.f32 "
        "{%0,%1,%2,%3}, {%4,%5,%6,%7}, {%8,%9}, {%0,%1,%2,%3};"
        : "+f"(d[0]), "+f"(d[1]), "+f"(d[2]), "+f"(d[3])
        : "r"(a[0]), "r"(a[1]), "r"(a[2]), "r"(a[3]), "r"(b[0]), "r"(b[1]));
}
// split two floats into packed bf16 hi / lo pairs
__device__ __forceinline__ void split2(float x, float y, uint32_t& hi, uint32_t& lo) {
    __nv_bfloat16 hx = __float2bfloat16(x), hy = __float2bfloat16(y);
    __nv_bfloat16 lx = __float2bfloat16(x - __bfloat162float(hx));
    __nv_bfloat16 ly = __float2bfloat16(y - __bfloat162float(hy));
    hi = ((uint32_t)__bfloat16_as_ushort(hy) << 16) | (uint32_t)__bfloat16_as_ushort(hx);
    lo = ((uint32_t)__bfloat16_as_ushort(ly) << 16) | (uint32_t)__bfloat16_as_ushort(lx);
}

// ---- pre-split weights into bf16 hi/lo ----
__global__ void k_wconv(const float* __restrict__ W1, const float* __restrict__ W2) {
    int i = blockIdx.x * blockDim.x + threadIdx.x;
    if (i < IND * HID) {
        float v = W1[i];
        __nv_bfloat16 h = __float2bfloat16(v);
        g_w1h[i] = h;
        g_w1l[i] = __float2bfloat16(v - __bfloat162float(h));
    } else if (i < IND * HID + HID * OUTD) {
        int j = i - IND * HID;
        float v = W2[j];
        __nv_bfloat16 h = __float2bfloat16(v);
        g_w2h[j] = h;
        g_w2l[j] = __float2bfloat16(v - __bfloat162float(h));
    }
}

// ============ bf16-split mma.sync GEMM: C = [relu](A@B + bias) ==============
// A: [M, KT] fp32 row-major (converted inline). B: pre-split bf16 hi/lo [KT, NT].
// BM=128, BN=NT (whole N in one block), BK=32.
template <int NT, int KT, int WGM, int WGN, int THREADS, bool RELU, bool DUAL>
__global__ void __launch_bounds__(THREADS, 1)
gemm_mma(const float* __restrict__ A, const __nv_bfloat16* __restrict__ Bh_g,
         const __nv_bfloat16* __restrict__ Bl_g, const float* __restrict__ bias,
         float* __restrict__ C, __half* __restrict__ H16, int M) {
    constexpr int BM = 128, BK = 32, BN = NT;
    constexpr int A_STR = BK + 8;            // bf16 elems (80B rows)
    constexpr int B_STR = BN + 8;            // (BN+8)*2 B rows, == 16 mod 128
    constexpr int ASZ = BM * A_STR * 2;      // bytes per A split tile
    constexpr int BSZ = BK * B_STR * 2;      // bytes per B split tile
    constexpr int WM = BM / WGM, WN = BN / WGN;
    constexpr int MF = WM / 16, NF = WN / 8;

    extern __shared__ char sm[];
    const uint32_t aAh = smem_u32(sm);
    const uint32_t aAl = aAh + ASZ;
    const uint32_t aBh = aAh + 2 * ASZ;
    const uint32_t aBl = aBh + BSZ;

    const int tid = threadIdx.x, wid = tid >> 5, lane = tid & 31;
    const int wm = wid / WGN, wn = wid % WGN;
    const int bm = blockIdx.x * BM;

    float acc[MF][NF][4] = {};

    for (int k0 = 0; k0 < KT; k0 += BK) {
        __syncthreads();
        // ---- A tile: fp32 -> bf16 hi/lo, [BM][BK] rows padded to A_STR ----
#pragma unroll
        for (int u = tid; u < BM * (BK / 4); u += THREADS) {
            int r = u >> 3, c4 = u & 7;
            int gr = bm + r;
            float4 v = make_float4(0.f, 0.f, 0.f, 0.f);
            if (gr < M) v = *(const float4*)(A + (size_t)gr * KT + k0 + c4 * 4);
            uint32_t h01, l01, h23, l23;
            split2(v.x, v.y, h01, l01);
            split2(v.z, v.w, h23, l23);
            uint32_t off = (uint32_t)r * (A_STR * 2) + c4 * 8;
            *(uint2*)(sm + (off))        = make_uint2(h01, h23);
            *(uint2*)(sm + (ASZ + off))  = make_uint2(l01, l23);
        }
        // ---- B tile: pre-split bf16, [BK][BN] rows padded to B_STR ----
#pragma unroll
        for (int u = tid; u < BK * (BN / 8); u += THREADS) {
            int r = u / (BN / 8), c8 = u % (BN / 8);
            size_t gsrc = (size_t)(k0 + r) * NT + c8 * 8;
            uint32_t off = 2 * ASZ + (uint32_t)r * (B_STR * 2) + c8 * 16;
            *(uint4*)(sm + off)       = *(const uint4*)(Bh_g + gsrc);
            *(uint4*)(sm + off + BSZ) = *(const uint4*)(Bl_g + gsrc);
        }
        __syncthreads();

        // ---- compute: two k16 substeps ----
#pragma unroll
        for (int ks = 0; ks < 2; ks++) {
            uint32_t ah[MF][4], al[MF][4];
#pragma unroll
            for (int mf = 0; mf < MF; mf++) {
                int row = wm * WM + mf * 16 + (lane & 15);
                uint32_t off = (uint32_t)row * (A_STR * 2) + ks * 32 + ((lane >> 4) << 4);
                ldsm4(ah[mf], aAh + off);
                ldsm4(al[mf], aAl + off);
            }
#pragma unroll
            for (int j = 0; j < NF / 2; j++) {
                int rB = ks * 16 + (lane & 15);
                int col = wn * WN + j * 16 + ((lane >> 4) << 3);
                uint32_t off = (uint32_t)rB * (B_STR * 2) + col * 2;
                uint32_t bh[4], bl[4];
                ldsm4t(bh, aBh + off);
                ldsm4t(bl, aBl + off);
#pragma unroll
                for (int mf = 0; mf < MF; mf++) {
                    mma16816(acc[mf][2 * j],     ah[mf], bh);
                    mma16816(acc[mf][2 * j],     ah[mf], bl);
                    mma16816(acc[mf][2 * j],     al[mf], bh);
                    mma16816(acc[mf][2 * j + 1], ah[mf], bh + 2);
                    mma16816(acc[mf][2 * j + 1], ah[mf], bl + 2);
                    mma16816(acc[mf][2 * j + 1], al[mf], bh + 2);
                }
            }
        }
    }

    // ---- epilogue ----
    const int grp = lane >> 2, qd = lane & 3;
#pragma unroll
    for (int mf = 0; mf < MF; mf++) {
#pragma unroll
        for (int nf = 0; nf < NF; nf++) {
            int col = wn * WN + nf * 8 + qd * 2;
            float bv0 = __ldg(bias + col), bv1 = __ldg(bias + col + 1);
            int r0 = bm + wm * WM + mf * 16 + grp;
#pragma unroll
            for (int h = 0; h < 2; h++) {
                int r = r0 + h * 8;
                if (r < M) {
                    float v0 = acc[mf][nf][2 * h + 0] + bv0;
                    float v1 = acc[mf][nf][2 * h + 1] + bv1;
                    if (RELU) { v0 = fmaxf(v0, 0.f); v1 = fmaxf(v1, 0.f); }
                    *(float2*)(C + (size_t)r * NT + col) = make_float2(v0, v1);
                    if (DUAL)
                        *(__half2*)(H16 + (size_t)r * NT + col) = __floats2half2_rn(v0, v1);
                }
            }
        }
    }
}

// ---------------- edge index access ----------------
__device__ __forceinline__ int edge_at(const void* p, int is64, long long i) {
    return is64 ? (int)((const long long*)p)[i] : ((const int*)p)[i];
}

__global__ void k_init(int n) {
    int i = blockIdx.x * blockDim.x + threadIdx.x;
    if (i < n) g_deg[i] = 1;
    if (i == 0) g_nonzero = 0;
}
__global__ void k_detect(const int* p) {
    int v = p[2 * threadIdx.x + 1];
    if (v != 0) atomicOr(&g_nonzero, 1);
}
__global__ void k_count(const void* e, int E) {
    int i = blockIdx.x * blockDim.x + threadIdx.x;
    if (i >= E) return;
    int is64 = (g_nonzero == 0);
    atomicAdd(&g_deg[edge_at(e, is64, (long long)E + i)], 1);
}
__global__ void k_dinv(int n) {
    int i = blockIdx.x * blockDim.x + threadIdx.x;
    if (i < n) g_dinv[i] = rsqrtf((float)g_deg[i]);
}
__global__ void k_scan1(int n) {
    __shared__ int ws[32];
    int b = blockIdx.x, t = threadIdx.x;
    int i = b * 1024 + t;
    int v = (i < n) ? g_deg[i] : 0;
    int lane = t & 31, wid = t >> 5;
    int x = v;
#pragma unroll
    for (int o = 1; o < 32; o <<= 1) { int y = __shfl_up_sync(0xffffffffu, x, o); if (lane >= o) x += y; }
    if (lane == 31) ws[wid] = x;
    __syncthreads();
    if (wid == 0) {
        int s = ws[lane];
#pragma unroll
        for (int o = 1; o < 32; o <<= 1) { int y = __shfl_up_sync(0xffffffffu, s, o); if (lane >= o) s += y; }
        ws[lane] = s;
    }
    __syncthreads();
    int off = wid ? ws[wid - 1] : 0;
    if (i < n) g_rowptr[i] = off + x - v;
    if (t == 1023) g_bsums[b] = ws[31];
}
__global__ void k_scan2(int nb) {
    __shared__ int ws[32];
    int t = threadIdx.x;
    int v = (t < nb) ? g_bsums[t] : 0;
    int lane = t & 31, wid = t >> 5;
    int x = v;
#pragma unroll
    for (int o = 1; o < 32; o <<= 1) { int y = __shfl_up_sync(0xffffffffu, x, o); if (lane >= o) x += y; }
    if (lane == 31) ws[wid] = x;
    __syncthreads();
    if (wid == 0) {
        int s = ws[lane];
#pragma unroll
        for (int o = 1; o < 32; o <<= 1) { int y = __shfl_up_sync(0xffffffffu, s, o); if (lane >= o) s += y; }
        ws[lane] = s;
    }
    __syncthreads();
    int off = wid ? ws[wid - 1] : 0;
    if (t < nb) g_bsums[t] = off + x - v;
}
__global__ void k_scan3(int n, int total) {
    int i = blockIdx.x * blockDim.x + threadIdx.x;
    if (i < n) {
        g_rowptr[i] += g_bsums[i >> 10];
        g_ctr[i] = g_rowptr[i];
    }
    if (i == 0) g_rowptr[n] = total;
}
__global__ void k_fill(const void* e, int E, int n) {
    int i = blockIdx.x * blockDim.x + threadIdx.x;
    if (i >= E + n) return;
    int is64 = (g_nonzero == 0);
    int s, d;
    if (i < E) { s = edge_at(e, is64, i); d = edge_at(e, is64, (long long)E + i); }
    else       { s = d = i - E; }
    int p = atomicAdd(&g_ctr[d], 1);
    g_col[p] = s;
    g_val[p] = g_dinv[s] * g_dinv[d];
}

// ---------------- fp16 propagation: one warp per destination row ------------
template <bool LAST>
__global__ void k_prop16(const __half* __restrict__ hin, const float* __restrict__ h0,
                         __half* __restrict__ hout, float* __restrict__ fout, int n) {
    int w = (blockIdx.x * blockDim.x + threadIdx.x) >> 5;
    if (w >= n) return;
    int lane = threadIdx.x & 31;
    int s = g_rowptr[w], e = g_rowptr[w + 1];
    float a0 = 0.f, a1 = 0.f;
    int i = s;
    for (; i + 1 < e; i += 2) {
        int   c0 = __ldg(&g_col[i]);     float w0 = __ldg(&g_val[i]);
        int   c1 = __ldg(&g_col[i + 1]); float w1 = __ldg(&g_val[i + 1]);
        float2 f0 = __half22float2(*(const __half2*)(hin + (size_t)c0 * OUTD + lane * 2));
        float2 f1 = __half22float2(*(const __half2*)(hin + (size_t)c1 * OUTD + lane * 2));
        a0 += w0 * f0.x + w1 * f1.x;
        a1 += w0 * f0.y + w1 * f1.y;
    }
    if (i < e) {
        int c = __ldg(&g_col[i]); float wv = __ldg(&g_val[i]);
        float2 f = __half22float2(*(const __half2*)(hin + (size_t)c * OUTD + lane * 2));
        a0 += wv * f.x; a1 += wv * f.y;
    }
    size_t o = (size_t)w * OUTD + lane * 2;
    float2 z = *(const float2*)(h0 + o);
    float r0 = 0.9f * a0 + 0.1f * z.x;
    float r1 = 0.9f * a1 + 0.1f * z.y;
    if (LAST) {
        *(float2*)(fout + o) = make_float2(r0, r1);
    } else {
        *(__half2*)(hout + o) = __floats2half2_rn(r0, r1);
    }
}

// ---------------- launch ----------------------------------------------------
extern "C" void kernel_launch(void* const* d_in, const int* in_sizes, int n_in,
                              void* d_out, int out_size) {
    const float* x  = (const float*)d_in[0];
    const void*  ei = d_in[1];
    const float* W1 = (const float*)d_in[2];
    const float* b1 = (const float*)d_in[3];
    const float* W2 = (const float*)d_in[4];
    const float* b2 = (const float*)d_in[5];
    float* out = (float*)d_out;

    int N = in_sizes[0] / IND;
    int E = in_sizes[1] / 2;

    void* p;
    cudaGetSymbolAddress(&p, g_h1);   float* h1 = (float*)p;
    cudaGetSymbolAddress(&p, g_h0);   float* h0 = (float*)p;
    cudaGetSymbolAddress(&p, g_h16a); __half* ha = (__half*)p;
    cudaGetSymbolAddress(&p, g_h16b); __half* hb = (__half*)p;
    cudaGetSymbolAddress(&p, g_w1h);  __nv_bfloat16* w1h = (__nv_bfloat16*)p;
    cudaGetSymbolAddress(&p, g_w1l);  __nv_bfloat16* w1l = (__nv_bfloat16*)p;
    cudaGetSymbolAddress(&p, g_w2h);  __nv_bfloat16* w2h = (__nv_bfloat16*)p;
    cudaGetSymbolAddress(&p, g_w2l);  __nv_bfloat16* w2l = (__nv_bfloat16*)p;

    int nb = (N + 1023) / 1024;

    // ---- CSR build ----
    k_init<<<(N + 255) / 256, 256>>>(N);
    k_detect<<<1, 1024>>>((const int*)ei);
    k_count<<<(E + 255) / 256, 256>>>(ei, E);
    k_dinv<<<(N + 255) / 256, 256>>>(N);
    k_scan1<<<nb, 1024>>>(N);
    k_scan2<<<1, 1024>>>(nb);
    k_scan3<<<nb, 1024>>>(N, E + N);
    k_fill<<<(E + N + 255) / 256, 256>>>(ei, E, N);

    // ---- weight pre-split ----
    int wtot = IND * HID + HID * OUTD;
    k_wconv<<<(wtot + 255) / 256, 256>>>(W1, W2);

    // ---- MLP via bf16-split mma.sync ----
    constexpr int SM1 = 2 * (128 * 40 * 2) + 2 * (32 * (HID + 8) * 2);   // 20480+33792
    constexpr int SM2 = 2 * (128 * 40 * 2) + 2 * (32 * (OUTD + 8) * 2);  // 20480+9216
    cudaFuncSetAttribute(gemm_mma<HID, IND, 4, 4, 512, true, false>,
                         cudaFuncAttributeMaxDynamicSharedMemorySize, SM1);
    cudaFuncSetAttribute(gemm_mma<OUTD, HID, 8, 1, 256, false, true>,
                         cudaFuncAttributeMaxDynamicSharedMemorySize, SM2);
    int gm = (N + 127) / 128;
    gemm_mma<HID, IND, 4, 4, 512, true, false><<<gm, 512, SM1>>>(
        x, w1h, w1l, b1, h1, nullptr, N);
    gemm_mma<OUTD, HID, 8, 1, 256, false, true><<<gm, 256, SM2>>>(
        h1, w2h, w2l, b2, h0, ha, N);

    // ---- K=10 fp16 propagation rounds ----
    __half* bufs[2] = {ha, hb};
    int blocks = (N * 32 + 255) / 256;
    for (int it = 0; it < 10; it++) {
        const __half* hin = bufs[it & 1];
        if (it == 9) {
            k_prop16<true><<<blocks, 256>>>(hin, h0, nullptr, out, N);
        } else {
            k_prop16<false><<<blocks, 256>>>(hin, h0, bufs[(it + 1) & 1], nullptr, N);
        }
    }
}

// round 4
// speedup vs baseline: 1.6867x; 1.2037x over previous
#include <cuda_runtime.h>
#include <cuda_bf16.h>
#include <cuda_fp16.h>
#include <cstdint>

// ---------------- Problem constants ----------------
static constexpr int MAXN = 100000;
static constexpr int MAXE = 3200000;
static constexpr int IND  = 512;
static constexpr int HID  = 256;
static constexpr int OUTD = 64;

// ---------------- Device scratch ----------------
__device__ int   g_deg[MAXN];
__device__ float g_dinv[MAXN];
__device__ int   g_rowptr[MAXN + 1];
__device__ int   g_ctr[MAXN];
__device__ int   g_bsums[1024];
__device__ int   g_nonzero;
__device__ int2  g_edge[MAXE + MAXN];      // {src col, weight bits}
__device__ __nv_bfloat16 g_w1h[IND * HID], g_w1l[IND * HID];
__device__ __nv_bfloat16 g_w2h[HID * OUTD], g_w2l[HID * OUTD];
__device__ float  g_h1[(size_t)MAXN * HID];
__device__ float  g_h0[(size_t)MAXN * OUTD];
__device__ __half g_h16a[(size_t)MAXN * OUTD];
__device__ __half g_h16b[(size_t)MAXN * OUTD];

// ================= helpers =================
__device__ __forceinline__ uint32_t smem_u32(const void* p) {
    uint32_t a;
    asm("{ .reg .u64 t; cvta.to.shared.u64 t, %1; cvt.u32.u64 %0, t; }" : "=r"(a) : "l"(p));
    return a;
}
__device__ __forceinline__ void ldsm4(uint32_t* r, uint32_t a) {
    asm volatile("ldmatrix.sync.aligned.m8n8.x4.shared.b16 {%0,%1,%2,%3}, [%4];"
        : "=r"(r[0]), "=r"(r[1]), "=r"(r[2]), "=r"(r[3]) : "r"(a));
}
__device__ __forceinline__ void ldsm4t(uint32_t* r, uint32_t a) {
    asm volatile("ldmatrix.sync.aligned.m8n8.x4.trans.shared.b16 {%0,%1,%2,%3}, [%4];"
        : "=r"(r[0]), "=r"(r[1]), "=r"(r[2]), "=r"(r[3]) : "r"(a));
}
__device__ __forceinline__ void mma16816(float* d, const uint32_t* a, const uint32_t* b) {
    asm volatile("mma.sync.aligned.m16n8k16.row.col.f32.bf16.bf16.f32 "
        "{%0,%1,%2,%3}, {%4,%5,%6,%7}, {%8,%9}, {%0,%1,%2,%3};"
        : "+f"(d[0]), "+f"(d[1]), "+f"(d[2]), "+f"(d[3])
        : "r"(a[0]), "r"(a[1]), "r"(a[2]), "r"(a[3]), "r"(b[0]), "r"(b[1]));
}
__device__ __forceinline__ void split2(float x, float y, uint32_t& hi, uint32_t& lo) {
    __nv_bfloat16 hx = __float2bfloat16(x), hy = __float2bfloat16(y);
    __nv_bfloat16 lx = __float2bfloat16(x - __bfloat162float(hx));
    __nv_bfloat16 ly = __float2bfloat16(y - __bfloat162float(hy));
    hi = ((uint32_t)__bfloat16_as_ushort(hy) << 16) | (uint32_t)__bfloat16_as_ushort(hx);
    lo = ((uint32_t)__bfloat16_as_ushort(ly) << 16) | (uint32_t)__bfloat16_as_ushort(lx);
}

// ---- pre-split weights into bf16 hi/lo ----
__global__ void k_wconv(const float* __restrict__ W1, const float* __restrict__ W2) {
    int i = blockIdx.x * blockDim.x + threadIdx.x;
    if (i < IND * HID) {
        float v = W1[i];
        __nv_bfloat16 h = __float2bfloat16(v);
        g_w1h[i] = h;
        g_w1l[i] = __float2bfloat16(v - __bfloat162float(h));
    } else if (i < IND * HID + HID * OUTD) {
        int j = i - IND * HID;
        float v = W2[j];
        __nv_bfloat16 h = __float2bfloat16(v);
        g_w2h[j] = h;
        g_w2l[j] = __float2bfloat16(v - __bfloat162float(h));
    }
}

// ============ bf16-split mma.sync GEMM with register-prefetch ===============
template <int NT, int KT, int WGM, int WGN, int THREADS, bool RELU, bool DUAL>
__global__ void __launch_bounds__(THREADS, 1)
gemm_mma(const float* __restrict__ A, const __nv_bfloat16* __restrict__ Bh_g,
         const __nv_bfloat16* __restrict__ Bl_g, const float* __restrict__ bias,
         float* __restrict__ C, __half* __restrict__ H16, int M) {
    constexpr int BM = 128, BK = 32, BN = NT;
    constexpr int A_STR = BK + 8;            // bf16 elems (80B rows)
    constexpr int B_STR = BN + 8;            // rows == 16 mod 128 B
    constexpr int ASZ = BM * A_STR * 2;
    constexpr int BSZ = BK * B_STR * 2;
    constexpr int WM = BM / WGM, WN = BN / WGN;
    constexpr int MF = WM / 16, NF = WN / 8;
    constexpr int NC = KT / BK;
    constexpr int A_IT = BM * (BK / 4) / THREADS;
    constexpr int B_IT = BK * (BN / 8) / THREADS;

    extern __shared__ char sm[];
    const uint32_t aAh = smem_u32(sm);
    const uint32_t aAl = aAh + ASZ;
    const uint32_t aBh = aAh + 2 * ASZ;
    const uint32_t aBl = aBh + BSZ;

    const int tid = threadIdx.x, wid = tid >> 5, lane = tid & 31;
    const int wm = wid / WGN, wn = wid % WGN;
    const int bm = blockIdx.x * BM;

    float acc[MF][NF][4] = {};
    float4 pa[A_IT];
    uint4  pbh[B_IT], pbl[B_IT];

    auto prefetch = [&](int k0) {
#pragma unroll
        for (int it = 0; it < A_IT; it++) {
            int u = tid + it * THREADS;
            int r = u >> 3, c4 = u & 7;
            int gr = bm + r;
            pa[it] = make_float4(0.f, 0.f, 0.f, 0.f);
            if (gr < M) pa[it] = *(const float4*)(A + (size_t)gr * KT + k0 + c4 * 4);
        }
#pragma unroll
        for (int it = 0; it < B_IT; it++) {
            int u = tid + it * THREADS;
            int r = u / (BN / 8), c8 = u % (BN / 8);
            size_t gsrc = (size_t)(k0 + r) * NT + c8 * 8;
            pbh[it] = *(const uint4*)(Bh_g + gsrc);
            pbl[it] = *(const uint4*)(Bl_g + gsrc);
        }
    };

    prefetch(0);

    for (int ic = 0; ic < NC; ic++) {
        __syncthreads();
        // ---- store prefetched tile (split A on the fly) ----
#pragma unroll
        for (int it = 0; it < A_IT; it++) {
            int u = tid + it * THREADS;
            int r = u >> 3, c4 = u & 7;
            uint32_t h01, l01, h23, l23;
            split2(pa[it].x, pa[it].y, h01, l01);
            split2(pa[it].z, pa[it].w, h23, l23);
            uint32_t off = (uint32_t)r * (A_STR * 2) + c4 * 8;
            *(uint2*)(sm + off)       = make_uint2(h01, h23);
            *(uint2*)(sm + ASZ + off) = make_uint2(l01, l23);
        }
#pragma unroll
        for (int it = 0; it < B_IT; it++) {
            int u = tid + it * THREADS;
            int r = u / (BN / 8), c8 = u % (BN / 8);
            uint32_t off = 2 * ASZ + (uint32_t)r * (B_STR * 2) + c8 * 16;
            *(uint4*)(sm + off)       = pbh[it];
            *(uint4*)(sm + off + BSZ) = pbl[it];
        }
        __syncthreads();

        if (ic + 1 < NC) prefetch((ic + 1) * BK);   // overlap with compute below

        // ---- compute: two k16 substeps ----
#pragma unroll
        for (int ks = 0; ks < 2; ks++) {
            uint32_t ah[MF][4], al[MF][4];
#pragma unroll
            for (int mf = 0; mf < MF; mf++) {
                int row = wm * WM + mf * 16 + (lane & 15);
                uint32_t off = (uint32_t)row * (A_STR * 2) + ks * 32 + ((lane >> 4) << 4);
                ldsm4(ah[mf], aAh + off);
                ldsm4(al[mf], aAl + off);
            }
#pragma unroll
            for (int j = 0; j < NF / 2; j++) {
                int rB = ks * 16 + (lane & 15);
                int col = wn * WN + j * 16 + ((lane >> 4) << 3);
                uint32_t off = (uint32_t)rB * (B_STR * 2) + col * 2;
                uint32_t bh[4], bl[4];
                ldsm4t(bh, aBh + off);
                ldsm4t(bl, aBl + off);
#pragma unroll
                for (int mf = 0; mf < MF; mf++) {
                    mma16816(acc[mf][2 * j],     ah[mf], bh);
                    mma16816(acc[mf][2 * j],     ah[mf], bl);
                    mma16816(acc[mf][2 * j],     al[mf], bh);
                    mma16816(acc[mf][2 * j + 1], ah[mf], bh + 2);
                    mma16816(acc[mf][2 * j + 1], ah[mf], bl + 2);
                    mma16816(acc[mf][2 * j + 1], al[mf], bh + 2);
                }
            }
        }
    }

    // ---- epilogue ----
    const int grp = lane >> 2, qd = lane & 3;
#pragma unroll
    for (int mf = 0; mf < MF; mf++) {
#pragma unroll
        for (int nf = 0; nf < NF; nf++) {
            int col = wn * WN + nf * 8 + qd * 2;
            float bv0 = __ldg(bias + col), bv1 = __ldg(bias + col + 1);
            int r0 = bm + wm * WM + mf * 16 + grp;
#pragma unroll
            for (int h = 0; h < 2; h++) {
                int r = r0 + h * 8;
                if (r < M) {
                    float v0 = acc[mf][nf][2 * h + 0] + bv0;
                    float v1 = acc[mf][nf][2 * h + 1] + bv1;
                    if (RELU) { v0 = fmaxf(v0, 0.f); v1 = fmaxf(v1, 0.f); }
                    *(float2*)(C + (size_t)r * NT + col) = make_float2(v0, v1);
                    if (DUAL)
                        *(__half2*)(H16 + (size_t)r * NT + col) = __floats2half2_rn(v0, v1);
                }
            }
        }
    }
}

// ---------------- edge index access ----------------
__device__ __forceinline__ int edge_at(const void* p, int is64, long long i) {
    return is64 ? (int)((const long long*)p)[i] : ((const int*)p)[i];
}

__global__ void k_init(int n) {
    int i = blockIdx.x * blockDim.x + threadIdx.x;
    if (i < n) g_deg[i] = 1;
    if (i == 0) g_nonzero = 0;
}
__global__ void k_detect(const int* p) {
    int v = p[2 * threadIdx.x + 1];
    if (v != 0) atomicOr(&g_nonzero, 1);
}
__global__ void k_count(const void* e, int E) {
    int i = blockIdx.x * blockDim.x + threadIdx.x;
    if (i >= E) return;
    int is64 = (g_nonzero == 0);
    atomicAdd(&g_deg[edge_at(e, is64, (long long)E + i)], 1);
}
__global__ void k_dinv(int n) {
    int i = blockIdx.x * blockDim.x + threadIdx.x;
    if (i < n) g_dinv[i] = rsqrtf((float)g_deg[i]);
}
__global__ void k_scan1(int n) {
    __shared__ int ws[32];
    int b = blockIdx.x, t = threadIdx.x;
    int i = b * 1024 + t;
    int v = (i < n) ? g_deg[i] : 0;
    int lane = t & 31, wid = t >> 5;
    int x = v;
#pragma unroll
    for (int o = 1; o < 32; o <<= 1) { int y = __shfl_up_sync(0xffffffffu, x, o); if (lane >= o) x += y; }
    if (lane == 31) ws[wid] = x;
    __syncthreads();
    if (wid == 0) {
        int s = ws[lane];
#pragma unroll
        for (int o = 1; o < 32; o <<= 1) { int y = __shfl_up_sync(0xffffffffu, s, o); if (lane >= o) s += y; }
        ws[lane] = s;
    }
    __syncthreads();
    int off = wid ? ws[wid - 1] : 0;
    if (i < n) g_rowptr[i] = off + x - v;
    if (t == 1023) g_bsums[b] = ws[31];
}
__global__ void k_scan2(int nb) {
    __shared__ int ws[32];
    int t = threadIdx.x;
    int v = (t < nb) ? g_bsums[t] : 0;
    int lane = t & 31, wid = t >> 5;
    int x = v;
#pragma unroll
    for (int o = 1; o < 32; o <<= 1) { int y = __shfl_up_sync(0xffffffffu, x, o); if (lane >= o) x += y; }
    if (lane == 31) ws[wid] = x;
    __syncthreads();
    if (wid == 0) {
        int s = ws[lane];
#pragma unroll
        for (int o = 1; o < 32; o <<= 1) { int y = __shfl_up_sync(0xffffffffu, s, o); if (lane >= o) s += y; }
        ws[lane] = s;
    }
    __syncthreads();
    int off = wid ? ws[wid - 1] : 0;
    if (t < nb) g_bsums[t] = off + x - v;
}
__global__ void k_scan3(int n, int total) {
    int i = blockIdx.x * blockDim.x + threadIdx.x;
    if (i < n) {
        g_rowptr[i] += g_bsums[i >> 10];
        g_ctr[i] = g_rowptr[i];
    }
    if (i == 0) g_rowptr[n] = total;
}
__global__ void k_fill(const void* e, int E, int n) {
    int i = blockIdx.x * blockDim.x + threadIdx.x;
    if (i >= E + n) return;
    int is64 = (g_nonzero == 0);
    int s, d;
    if (i < E) { s = edge_at(e, is64, i); d = edge_at(e, is64, (long long)E + i); }
    else       { s = d = i - E; }
    int p = atomicAdd(&g_ctr[d], 1);
    float v = g_dinv[s] * g_dinv[d];
    g_edge[p] = make_int2(s, __float_as_int(v));
}

// -------- fp16 propagation: 1 warp/row, 4 edges in flight (LDG.128) ---------
template <bool LAST>
__global__ void k_prop16(const __half* __restrict__ hin, const float* __restrict__ h0,
                         __half* __restrict__ hout, float* __restrict__ fout, int n) {
    int w = (blockIdx.x * blockDim.x + threadIdx.x) >> 5;
    if (w >= n) return;
    int lane = threadIdx.x & 31;
    int g = lane >> 3, sl = lane & 7;      // 4 groups of 8 lanes
    int s = g_rowptr[w], e = g_rowptr[w + 1];
    float acc[8] = {};

#pragma unroll 2
    for (int i = s + g; i < e; i += 4) {
        int2 cv = __ldg(&g_edge[i]);                    // broadcast within group
        float wv = __int_as_float(cv.y);
        const uint4* row = (const uint4*)(hin + (size_t)cv.x * OUTD);
        uint4 pk = __ldg(row + sl);                     // 16B = 8 halves
        float2 f0 = __half22float2(*(const __half2*)&pk.x);
        float2 f1 = __half22float2(*(const __half2*)&pk.y);
        float2 f2 = __half22float2(*(const __half2*)&pk.z);
        float2 f3 = __half22float2(*(const __half2*)&pk.w);
        acc[0] += wv * f0.x; acc[1] += wv * f0.y;
        acc[2] += wv * f1.x; acc[3] += wv * f1.y;
        acc[4] += wv * f2.x; acc[5] += wv * f2.y;
        acc[6] += wv * f3.x; acc[7] += wv * f3.y;
    }
    // combine the 4 groups (cols owned identically per sl across groups)
#pragma unroll
    for (int j = 0; j < 8; j++) {
        acc[j] += __shfl_xor_sync(0xffffffffu, acc[j], 8);
        acc[j] += __shfl_xor_sync(0xffffffffu, acc[j], 16);
    }
    if (g == 0) {
        size_t o = (size_t)w * OUTD + sl * 8;
        float4 z0 = *(const float4*)(h0 + o);
        float4 z1 = *(const float4*)(h0 + o + 4);
        float r[8];
        r[0] = 0.9f * acc[0] + 0.1f * z0.x; r[1] = 0.9f * acc[1] + 0.1f * z0.y;
        r[2] = 0.9f * acc[2] + 0.1f * z0.z; r[3] = 0.9f * acc[3] + 0.1f * z0.w;
        r[4] = 0.9f * acc[4] + 0.1f * z1.x; r[5] = 0.9f * acc[5] + 0.1f * z1.y;
        r[6] = 0.9f * acc[6] + 0.1f * z1.z; r[7] = 0.9f * acc[7] + 0.1f * z1.w;
        if (LAST) {
            *(float4*)(fout + o)     = make_float4(r[0], r[1], r[2], r[3]);
            *(float4*)(fout + o + 4) = make_float4(r[4], r[5], r[6], r[7]);
        } else {
            uint4 pk;
            *(__half2*)&pk.x = __floats2half2_rn(r[0], r[1]);
            *(__half2*)&pk.y = __floats2half2_rn(r[2], r[3]);
            *(__half2*)&pk.z = __floats2half2_rn(r[4], r[5]);
            *(__half2*)&pk.w = __floats2half2_rn(r[6], r[7]);
            *(uint4*)(hout + (size_t)w * OUTD + sl * 8) = pk;
        }
    }
}

// ---------------- launch ----------------------------------------------------
extern "C" void kernel_launch(void* const* d_in, const int* in_sizes, int n_in,
                              void* d_out, int out_size) {
    const float* x  = (const float*)d_in[0];
    const void*  ei = d_in[1];
    const float* W1 = (const float*)d_in[2];
    const float* b1 = (const float*)d_in[3];
    const float* W2 = (const float*)d_in[4];
    const float* b2 = (const float*)d_in[5];
    float* out = (float*)d_out;

    int N = in_sizes[0] / IND;
    int E = in_sizes[1] / 2;

    void* p;
    cudaGetSymbolAddress(&p, g_h1);   float* h1 = (float*)p;
    cudaGetSymbolAddress(&p, g_h0);   float* h0 = (float*)p;
    cudaGetSymbolAddress(&p, g_h16a); __half* ha = (__half*)p;
    cudaGetSymbolAddress(&p, g_h16b); __half* hb = (__half*)p;
    cudaGetSymbolAddress(&p, g_w1h);  __nv_bfloat16* w1h = (__nv_bfloat16*)p;
    cudaGetSymbolAddress(&p, g_w1l);  __nv_bfloat16* w1l = (__nv_bfloat16*)p;
    cudaGetSymbolAddress(&p, g_w2h);  __nv_bfloat16* w2h = (__nv_bfloat16*)p;
    cudaGetSymbolAddress(&p, g_w2l);  __nv_bfloat16* w2l = (__nv_bfloat16*)p;

    int nb = (N + 1023) / 1024;
    int gm = (N + 127) / 128;
    int wtot = IND * HID + HID * OUTD;

    constexpr int SM1 = 2 * (128 * 40 * 2) + 2 * (32 * (HID + 8) * 2);
    constexpr int SM2 = 2 * (128 * 40 * 2) + 2 * (32 * (OUTD + 8) * 2);
    cudaFuncSetAttribute(gemm_mma<HID, IND, 4, 4, 512, true, false>,
                         cudaFuncAttributeMaxDynamicSharedMemorySize, SM1);
    cudaFuncSetAttribute(gemm_mma<OUTD, HID, 8, 1, 256, false, true>,
                         cudaFuncAttributeMaxDynamicSharedMemorySize, SM2);

    // Launch order puts gemm1 at slot 4 (the ncu-captured launch).
    k_wconv<<<(wtot + 255) / 256, 256>>>(W1, W2);                       // 1
    k_init<<<(N + 255) / 256, 256>>>(N);                                // 2
    k_detect<<<1, 1024>>>((const int*)ei);                              // 3
    gemm_mma<HID, IND, 4, 4, 512, true, false><<<gm, 512, SM1>>>(       // 4
        x, w1h, w1l, b1, h1, nullptr, N);
    k_count<<<(E + 255) / 256, 256>>>(ei, E);                           // 5
    k_dinv<<<(N + 255) / 256, 256>>>(N);                                // 6
    k_scan1<<<nb, 1024>>>(N);                                           // 7
    k_scan2<<<1, 1024>>>(nb);                                           // 8
    k_scan3<<<nb, 1024>>>(N, E + N);                                    // 9
    gemm_mma<OUTD, HID, 8, 1, 256, false, true><<<gm, 256, SM2>>>(      // 10
        h1, w2h, w2l, b2, h0, ha, N);
    k_fill<<<(E + N + 255) / 256, 256>>>(ei, E, N);                     // 11

    __half* bufs[2] = {ha, hb};
    int blocks = (N * 32 + 255) / 256;
    for (int it = 0; it < 10; it++) {
        const __half* hin = bufs[it & 1];
        if (it == 9) {
            k_prop16<true><<<blocks, 256>>>(hin, h0, nullptr, out, N);
        } else {
            k_prop16<false><<<blocks, 256>>>(hin, h0, bufs[(it + 1) & 1], nullptr, N);
        }
    }
}

// round 5
// speedup vs baseline: 2.1280x; 1.2616x over previous
#include <cuda_runtime.h>
#include <cuda_bf16.h>
#include <cuda_fp16.h>
#include <cstdint>

// ---------------- Problem constants ----------------
static constexpr int MAXN = 100000;
static constexpr int MAXE = 3200000;
static constexpr int IND  = 512;
static constexpr int HID  = 256;
static constexpr int OUTD = 64;

// ---------------- Device scratch ----------------
__device__ int   g_deg[MAXN];
__device__ float g_dinv[MAXN];
__device__ int   g_rowptr[MAXN + 1];
__device__ int   g_ctr[MAXN];
__device__ int   g_bsums[1024];
__device__ int   g_nonzero;
__device__ int2  g_edge[MAXE + MAXN];      // {src col, weight bits}
__device__ __half g_w1f[IND * HID];
__device__ __half g_w2f[HID * OUTD];
__device__ float  g_h1[(size_t)MAXN * HID];
__device__ float  g_h0[(size_t)MAXN * OUTD];
__device__ __half g_h16a[(size_t)MAXN * OUTD];
__device__ __half g_h16b[(size_t)MAXN * OUTD];

// ================= helpers =================
__device__ __forceinline__ uint32_t smem_u32(const void* p) {
    uint32_t a;
    asm("{ .reg .u64 t; cvta.to.shared.u64 t, %1; cvt.u32.u64 %0, t; }" : "=r"(a) : "l"(p));
    return a;
}
__device__ __forceinline__ void ldsm4(uint32_t* r, uint32_t a) {
    asm volatile("ldmatrix.sync.aligned.m8n8.x4.shared.b16 {%0,%1,%2,%3}, [%4];"
        : "=r"(r[0]), "=r"(r[1]), "=r"(r[2]), "=r"(r[3]) : "r"(a));
}
__device__ __forceinline__ void ldsm4t(uint32_t* r, uint32_t a) {
    asm volatile("ldmatrix.sync.aligned.m8n8.x4.trans.shared.b16 {%0,%1,%2,%3}, [%4];"
        : "=r"(r[0]), "=r"(r[1]), "=r"(r[2]), "=r"(r[3]) : "r"(a));
}
__device__ __forceinline__ void mma16816f(float* d, const uint32_t* a, const uint32_t* b) {
    asm volatile("mma.sync.aligned.m16n8k16.row.col.f32.f16.f16.f32 "
        "{%0,%1,%2,%3}, {%4,%5,%6,%7}, {%8,%9}, {%0,%1,%2,%3};"
        : "+f"(d[0]), "+f"(d[1]), "+f"(d[2]), "+f"(d[3])
        : "r"(a[0]), "r"(a[1]), "r"(a[2]), "r"(a[3]), "r"(b[0]), "r"(b[1]));
}

// ---- convert weights to fp16 ----
__global__ void k_wconv(const float* __restrict__ W1, const float* __restrict__ W2) {
    int i = blockIdx.x * blockDim.x + threadIdx.x;
    if (i < IND * HID) {
        g_w1f[i] = __float2half_rn(W1[i]);
    } else if (i < IND * HID + HID * OUTD) {
        int j = i - IND * HID;
        g_w2f[j] = __float2half_rn(W2[j]);
    }
}

// ============ fp16 mma.sync GEMM with register-prefetch =====================
// A: [M, KT] fp32 row-major (converted inline). B: fp16 [KT, NT].
template <int NT, int KT, int WGM, int WGN, int THREADS, bool RELU, bool DUAL>
__global__ void __launch_bounds__(THREADS, 1)
gemm_fp16(const float* __restrict__ A, const __half* __restrict__ Bg,
          const float* __restrict__ bias, float* __restrict__ C,
          __half* __restrict__ H16, int M) {
    constexpr int BM = 128, BK = 32, BN = NT;
    constexpr int A_STR = BK + 8;            // fp16 elems (80B rows)
    constexpr int B_STR = BN + 8;            // rows == 16 mod 128 B
    constexpr int ASZ = BM * A_STR * 2;
    constexpr int WM = BM / WGM, WN = BN / WGN;
    constexpr int MF = WM / 16, NF = WN / 8;
    constexpr int NC = KT / BK;
    constexpr int A_IT = BM * (BK / 4) / THREADS;
    constexpr int B_IT = BK * (BN / 8) / THREADS;

    extern __shared__ char sm[];
    const uint32_t aA = smem_u32(sm);
    const uint32_t aB = aA + ASZ;

    const int tid = threadIdx.x, wid = tid >> 5, lane = tid & 31;
    const int wm = wid / WGN, wn = wid % WGN;
    const int bm = blockIdx.x * BM;

    float acc[MF][NF][4] = {};
    float4 pa[A_IT];
    uint4  pb[B_IT];

    auto prefetch = [&](int k0) {
#pragma unroll
        for (int it = 0; it < A_IT; it++) {
            int u = tid + it * THREADS;
            int r = u >> 3, c4 = u & 7;
            int gr = bm + r;
            pa[it] = make_float4(0.f, 0.f, 0.f, 0.f);
            if (gr < M) pa[it] = *(const float4*)(A + (size_t)gr * KT + k0 + c4 * 4);
        }
#pragma unroll
        for (int it = 0; it < B_IT; it++) {
            int u = tid + it * THREADS;
            int r = u / (BN / 8), c8 = u % (BN / 8);
            pb[it] = *(const uint4*)(Bg + (size_t)(k0 + r) * NT + c8 * 8);
        }
    };

    prefetch(0);

    for (int ic = 0; ic < NC; ic++) {
        __syncthreads();
#pragma unroll
        for (int it = 0; it < A_IT; it++) {
            int u = tid + it * THREADS;
            int r = u >> 3, c4 = u & 7;
            __half2 h01 = __floats2half2_rn(pa[it].x, pa[it].y);
            __half2 h23 = __floats2half2_rn(pa[it].z, pa[it].w);
            *(uint2*)(sm + (uint32_t)r * (A_STR * 2) + c4 * 8) =
                make_uint2(*(uint32_t*)&h01, *(uint32_t*)&h23);
        }
#pragma unroll
        for (int it = 0; it < B_IT; it++) {
            int u = tid + it * THREADS;
            int r = u / (BN / 8), c8 = u % (BN / 8);
            *(uint4*)(sm + ASZ + (uint32_t)r * (B_STR * 2) + c8 * 16) = pb[it];
        }
        __syncthreads();

        if (ic + 1 < NC) prefetch((ic + 1) * BK);   // overlap with compute

#pragma unroll
        for (int ks = 0; ks < 2; ks++) {
            uint32_t ah[MF][4];
#pragma unroll
            for (int mf = 0; mf < MF; mf++) {
                int row = wm * WM + mf * 16 + (lane & 15);
                ldsm4(ah[mf], aA + (uint32_t)row * (A_STR * 2) + ks * 32 + ((lane >> 4) << 4));
            }
#pragma unroll
            for (int j = 0; j < NF / 2; j++) {
                int rB = ks * 16 + (lane & 15);
                int col = wn * WN + j * 16 + ((lane >> 4) << 3);
                uint32_t bh[4];
                ldsm4t(bh, aB + (uint32_t)rB * (B_STR * 2) + col * 2);
#pragma unroll
                for (int mf = 0; mf < MF; mf++) {
                    mma16816f(acc[mf][2 * j],     ah[mf], bh);
                    mma16816f(acc[mf][2 * j + 1], ah[mf], bh + 2);
                }
            }
        }
    }

    // ---- epilogue ----
    const int grp = lane >> 2, qd = lane & 3;
#pragma unroll
    for (int mf = 0; mf < MF; mf++) {
#pragma unroll
        for (int nf = 0; nf < NF; nf++) {
            int col = wn * WN + nf * 8 + qd * 2;
            float bv0 = __ldg(bias + col), bv1 = __ldg(bias + col + 1);
            int r0 = bm + wm * WM + mf * 16 + grp;
#pragma unroll
            for (int h = 0; h < 2; h++) {
                int r = r0 + h * 8;
                if (r < M) {
                    float v0 = acc[mf][nf][2 * h + 0] + bv0;
                    float v1 = acc[mf][nf][2 * h + 1] + bv1;
                    if (RELU) { v0 = fmaxf(v0, 0.f); v1 = fmaxf(v1, 0.f); }
                    *(float2*)(C + (size_t)r * NT + col) = make_float2(v0, v1);
                    if (DUAL)
                        *(__half2*)(H16 + (size_t)r * NT + col) = __floats2half2_rn(v0, v1);
                }
            }
        }
    }
}

// ---------------- edge index access ----------------
__device__ __forceinline__ int edge_at(const void* p, int is64, long long i) {
    return is64 ? (int)((const long long*)p)[i] : ((const int*)p)[i];
}

__global__ void k_init(int n) {
    int i = blockIdx.x * blockDim.x + threadIdx.x;
    if (i < n) g_deg[i] = 1;
    if (i == 0) g_nonzero = 0;
}
__global__ void k_detect(const int* p) {
    int v = p[2 * threadIdx.x + 1];
    if (v != 0) atomicOr(&g_nonzero, 1);
}
__global__ void k_count(const void* e, int E) {
    int i = blockIdx.x * blockDim.x + threadIdx.x;
    if (i >= E) return;
    int is64 = (g_nonzero == 0);
    atomicAdd(&g_deg[edge_at(e, is64, (long long)E + i)], 1);
}
__global__ void k_dinv(int n) {
    int i = blockIdx.x * blockDim.x + threadIdx.x;
    if (i < n) g_dinv[i] = rsqrtf((float)g_deg[i]);
}
__global__ void k_scan1(int n) {
    __shared__ int ws[32];
    int b = blockIdx.x, t = threadIdx.x;
    int i = b * 1024 + t;
    int v = (i < n) ? g_deg[i] : 0;
    int lane = t & 31, wid = t >> 5;
    int x = v;
#pragma unroll
    for (int o = 1; o < 32; o <<= 1) { int y = __shfl_up_sync(0xffffffffu, x, o); if (lane >= o) x += y; }
    if (lane == 31) ws[wid] = x;
    __syncthreads();
    if (wid == 0) {
        int s = ws[lane];
#pragma unroll
        for (int o = 1; o < 32; o <<= 1) { int y = __shfl_up_sync(0xffffffffu, s, o); if (lane >= o) s += y; }
        ws[lane] = s;
    }
    __syncthreads();
    int off = wid ? ws[wid - 1] : 0;
    if (i < n) g_rowptr[i] = off + x - v;
    if (t == 1023) g_bsums[b] = ws[31];
}
__global__ void k_scan2(int nb) {
    __shared__ int ws[32];
    int t = threadIdx.x;
    int v = (t < nb) ? g_bsums[t] : 0;
    int lane = t & 31, wid = t >> 5;
    int x = v;
#pragma unroll
    for (int o = 1; o < 32; o <<= 1) { int y = __shfl_up_sync(0xffffffffu, x, o); if (lane >= o) x += y; }
    if (lane == 31) ws[wid] = x;
    __syncthreads();
    if (wid == 0) {
        int s = ws[lane];
#pragma unroll
        for (int o = 1; o < 32; o <<= 1) { int y = __shfl_up_sync(0xffffffffu, s, o); if (lane >= o) s += y; }
        ws[lane] = s;
    }
    __syncthreads();
    int off = wid ? ws[wid - 1] : 0;
    if (t < nb) g_bsums[t] = off + x - v;
}
__global__ void k_scan3(int n, int total) {
    int i = blockIdx.x * blockDim.x + threadIdx.x;
    if (i < n) {
        g_rowptr[i] += g_bsums[i >> 10];
        g_ctr[i] = g_rowptr[i];
    }
    if (i == 0) g_rowptr[n] = total;
}
__global__ void k_fill(const void* e, int E, int n) {
    int i = blockIdx.x * blockDim.x + threadIdx.x;
    if (i >= E + n) return;
    int is64 = (g_nonzero == 0);
    int s, d;
    if (i < E) { s = edge_at(e, is64, i); d = edge_at(e, is64, (long long)E + i); }
    else       { s = d = i - E; }
    int p = atomicAdd(&g_ctr[d], 1);
    float v = g_dinv[s] * g_dinv[d];
    g_edge[p] = make_int2(s, __float_as_int(v));
}

// -------- fp16 propagation: 1 warp/row, 4 edges in flight (LDG.128) ---------
template <bool LAST>
__global__ void k_prop16(const __half* __restrict__ hin, const float* __restrict__ h0,
                         __half* __restrict__ hout, float* __restrict__ fout, int n) {
    int w = (blockIdx.x * blockDim.x + threadIdx.x) >> 5;
    if (w >= n) return;
    int lane = threadIdx.x & 31;
    int g = lane >> 3, sl = lane & 7;      // 4 groups of 8 lanes
    int s = g_rowptr[w], e = g_rowptr[w + 1];
    float acc[8] = {};

#pragma unroll 2
    for (int i = s + g; i < e; i += 4) {
        int2 cv = __ldg(&g_edge[i]);
        float wv = __int_as_float(cv.y);
        const uint4* row = (const uint4*)(hin + (size_t)cv.x * OUTD);
        uint4 pk = __ldg(row + sl);
        float2 f0 = __half22float2(*(const __half2*)&pk.x);
        float2 f1 = __half22float2(*(const __half2*)&pk.y);
        float2 f2 = __half22float2(*(const __half2*)&pk.z);
        float2 f3 = __half22float2(*(const __half2*)&pk.w);
        acc[0] += wv * f0.x; acc[1] += wv * f0.y;
        acc[2] += wv * f1.x; acc[3] += wv * f1.y;
        acc[4] += wv * f2.x; acc[5] += wv * f2.y;
        acc[6] += wv * f3.x; acc[7] += wv * f3.y;
    }
#pragma unroll
    for (int j = 0; j < 8; j++) {
        acc[j] += __shfl_xor_sync(0xffffffffu, acc[j], 8);
        acc[j] += __shfl_xor_sync(0xffffffffu, acc[j], 16);
    }
    if (g == 0) {
        size_t o = (size_t)w * OUTD + sl * 8;
        float4 z0 = *(const float4*)(h0 + o);
        float4 z1 = *(const float4*)(h0 + o + 4);
        float r[8];
        r[0] = 0.9f * acc[0] + 0.1f * z0.x; r[1] = 0.9f * acc[1] + 0.1f * z0.y;
        r[2] = 0.9f * acc[2] + 0.1f * z0.z; r[3] = 0.9f * acc[3] + 0.1f * z0.w;
        r[4] = 0.9f * acc[4] + 0.1f * z1.x; r[5] = 0.9f * acc[5] + 0.1f * z1.y;
        r[6] = 0.9f * acc[6] + 0.1f * z1.z; r[7] = 0.9f * acc[7] + 0.1f * z1.w;
        if (LAST) {
            *(float4*)(fout + o)     = make_float4(r[0], r[1], r[2], r[3]);
            *(float4*)(fout + o + 4) = make_float4(r[4], r[5], r[6], r[7]);
        } else {
            uint4 pk;
            *(__half2*)&pk.x = __floats2half2_rn(r[0], r[1]);
            *(__half2*)&pk.y = __floats2half2_rn(r[2], r[3]);
            *(__half2*)&pk.z = __floats2half2_rn(r[4], r[5]);
            *(__half2*)&pk.w = __floats2half2_rn(r[6], r[7]);
            *(uint4*)(hout + (size_t)w * OUTD + sl * 8) = pk;
        }
    }
}

// ---------------- launch ----------------------------------------------------
extern "C" void kernel_launch(void* const* d_in, const int* in_sizes, int n_in,
                              void* d_out, int out_size) {
    const float* x  = (const float*)d_in[0];
    const void*  ei = d_in[1];
    const float* W1 = (const float*)d_in[2];
    const float* b1 = (const float*)d_in[3];
    const float* W2 = (const float*)d_in[4];
    const float* b2 = (const float*)d_in[5];
    float* out = (float*)d_out;

    int N = in_sizes[0] / IND;
    int E = in_sizes[1] / 2;

    void* p;
    cudaGetSymbolAddress(&p, g_h1);   float* h1 = (float*)p;
    cudaGetSymbolAddress(&p, g_h0);   float* h0 = (float*)p;
    cudaGetSymbolAddress(&p, g_h16a); __half* ha = (__half*)p;
    cudaGetSymbolAddress(&p, g_h16b); __half* hb = (__half*)p;
    cudaGetSymbolAddress(&p, g_w1f);  __half* w1f = (__half*)p;
    cudaGetSymbolAddress(&p, g_w2f);  __half* w2f = (__half*)p;

    int nb = (N + 1023) / 1024;
    int gm = (N + 127) / 128;
    int wtot = IND * HID + HID * OUTD;

    constexpr int SM1 = 128 * 40 * 2 + 32 * (HID + 8) * 2;   // 10240+16896
    constexpr int SM2 = 128 * 40 * 2 + 32 * (OUTD + 8) * 2;  // 10240+4608
    cudaFuncSetAttribute(gemm_fp16<HID, IND, 4, 4, 512, true, false>,
                         cudaFuncAttributeMaxDynamicSharedMemorySize, SM1);
    cudaFuncSetAttribute(gemm_fp16<OUTD, HID, 8, 1, 256, false, true>,
                         cudaFuncAttributeMaxDynamicSharedMemorySize, SM2);

    // Launch order keeps gemm1 at slot 4 (the ncu-captured launch).
    k_wconv<<<(wtot + 255) / 256, 256>>>(W1, W2);                       // 1
    k_init<<<(N + 255) / 256, 256>>>(N);                                // 2
    k_detect<<<1, 1024>>>((const int*)ei);                              // 3
    gemm_fp16<HID, IND, 4, 4, 512, true, false><<<gm, 512, SM1>>>(      // 4
        x, w1f, b1, h1, nullptr, N);
    k_count<<<(E + 255) / 256, 256>>>(ei, E);                           // 5
    k_dinv<<<(N + 255) / 256, 256>>>(N);                                // 6
    k_scan1<<<nb, 1024>>>(N);                                           // 7
    k_scan2<<<1, 1024>>>(nb);                                           // 8
    k_scan3<<<nb, 1024>>>(N, E + N);                                    // 9
    gemm_fp16<OUTD, HID, 8, 1, 256, false, true><<<gm, 256, SM2>>>(     // 10
        h1, w2f, b2, h0, ha, N);
    k_fill<<<(E + N + 255) / 256, 256>>>(ei, E, N);                     // 11

    __half* bufs[2] = {ha, hb};
    int blocks = (N * 32 + 255) / 256;
    for (int it = 0; it < 10; it++) {
        const __half* hin = bufs[it & 1];
        if (it == 9) {
            k_prop16<true><<<blocks, 256>>>(hin, h0, nullptr, out, N);
        } else {
            k_prop16<false><<<blocks, 256>>>(hin, h0, bufs[(it + 1) & 1], nullptr, N);
        }
    }
}

// round 7
// speedup vs baseline: 2.1317x; 1.0018x over previous
#include <cuda_runtime.h>
#include <cuda_bf16.h>
#include <cuda_fp16.h>
#include <cstdint>

// ---------------- Problem constants ----------------
static constexpr int MAXN = 100000;
static constexpr int MAXE = 3200000;
static constexpr int IND  = 512;
static constexpr int HID  = 256;
static constexpr int OUTD = 64;

// ---------------- Device scratch ----------------
__device__ int   g_deg[MAXN];
__device__ float g_dinv[MAXN];
__device__ int   g_rowptr[MAXN + 1];
__device__ int   g_ctr[MAXN];
__device__ int   g_bsums[1024];
__device__ int   g_nonzero;               // zero-initialized; monotonic (never reset)
__device__ int2  g_edge[MAXE + MAXN];     // {src col, weight bits}
__device__ __half g_w1f[IND * HID];
__device__ __half g_w2f[HID * OUTD];
__device__ float  g_h1[(size_t)MAXN * HID];
__device__ float  g_h0[(size_t)MAXN * OUTD];
__device__ __half g_h16a[(size_t)MAXN * OUTD];
__device__ __half g_h16b[(size_t)MAXN * OUTD];

// ================= helpers =================
__device__ __forceinline__ uint32_t smem_u32(const void* p) {
    uint32_t a;
    asm("{ .reg .u64 t; cvta.to.shared.u64 t, %1; cvt.u32.u64 %0, t; }" : "=r"(a) : "l"(p));
    return a;
}
__device__ __forceinline__ void ldsm4(uint32_t* r, uint32_t a) {
    asm volatile("ldmatrix.sync.aligned.m8n8.x4.shared.b16 {%0,%1,%2,%3}, [%4];"
        : "=r"(r[0]), "=r"(r[1]), "=r"(r[2]), "=r"(r[3]) : "r"(a));
}
__device__ __forceinline__ void ldsm4t(uint32_t* r, uint32_t a) {
    asm volatile("ldmatrix.sync.aligned.m8n8.x4.trans.shared.b16 {%0,%1,%2,%3}, [%4];"
        : "=r"(r[0]), "=r"(r[1]), "=r"(r[2]), "=r"(r[3]) : "r"(a));
}
__device__ __forceinline__ void mma16816f(float* d, const uint32_t* a, const uint32_t* b) {
    asm volatile("mma.sync.aligned.m16n8k16.row.col.f32.f16.f16.f32 "
        "{%0,%1,%2,%3}, {%4,%5,%6,%7}, {%8,%9}, {%0,%1,%2,%3};"
        : "+f"(d[0]), "+f"(d[1]), "+f"(d[2]), "+f"(d[3])
        : "r"(a[0]), "r"(a[1]), "r"(a[2]), "r"(a[3]), "r"(b[0]), "r"(b[1]));
}

// ---- convert weights to fp16 ----
__global__ void k_wconv(const float* __restrict__ W1, const float* __restrict__ W2) {
    int i = blockIdx.x * blockDim.x + threadIdx.x;
    if (i < IND * HID) {
        g_w1f[i] = __float2half_rn(W1[i]);
    } else if (i < IND * HID + HID * OUTD) {
        int j = i - IND * HID;
        g_w2f[j] = __float2half_rn(W2[j]);
    }
}

// ============ fp16 mma.sync GEMM, double-buffered SMEM ======================
// A: [M, KT] fp32 row-major (converted inline). B: fp16 [KT, NT].
template <int NT, int KT, int WGM, int WGN, int THREADS, bool RELU, bool DUAL>
__global__ void __launch_bounds__(THREADS, 1)
gemm_fp16(const float* __restrict__ A, const __half* __restrict__ Bg,
          const float* __restrict__ bias, float* __restrict__ C,
          __half* __restrict__ H16, int M) {
    constexpr int BM = 128, BK = 32, BN = NT;
    constexpr int A_STR = BK + 8;            // fp16 elems (80B rows)
    constexpr int B_STR = BN + 8;            // rows == 16 mod 128 B
    constexpr int ASZ = BM * A_STR * 2;
    constexpr int BSZ = BK * B_STR * 2;
    constexpr int BUF = ASZ + BSZ;
    constexpr int WM = BM / WGM, WN = BN / WGN;
    constexpr int MF = WM / 16, NF = WN / 8;
    constexpr int NC = KT / BK;
    constexpr int A_IT = BM * (BK / 4) / THREADS;
    constexpr int B_IT = BK * (BN / 8) / THREADS;

    extern __shared__ char sm[];
    const uint32_t aBase = smem_u32(sm);

    const int tid = threadIdx.x, wid = tid >> 5, lane = tid & 31;
    const int wm = wid / WGN, wn = wid % WGN;
    const int bm = blockIdx.x * BM;

    float acc[MF][NF][4] = {};
    float4 pa[A_IT];
    uint4  pb[B_IT];

    auto prefetch = [&](int k0) {            // k0 = element offset into K
#pragma unroll
        for (int it = 0; it < A_IT; it++) {
            int u = tid + it * THREADS;
            int r = u >> 3, c4 = u & 7;
            int gr = bm + r;
            pa[it] = make_float4(0.f, 0.f, 0.f, 0.f);
            if (gr < M) pa[it] = *(const float4*)(A + (size_t)gr * KT + k0 + c4 * 4);
        }
#pragma unroll
        for (int it = 0; it < B_IT; it++) {
            int u = tid + it * THREADS;
            int r = u / (BN / 8), c8 = u % (BN / 8);
            pb[it] = *(const uint4*)(Bg + (size_t)(k0 + r) * NT + c8 * 8);
        }
    };

    auto store_smem = [&](int b) {
        uint32_t boff = (uint32_t)b * BUF;
#pragma unroll
        for (int it = 0; it < A_IT; it++) {
            int u = tid + it * THREADS;
            int r = u >> 3, c4 = u & 7;
            __half2 h01 = __floats2half2_rn(pa[it].x, pa[it].y);
            __half2 h23 = __floats2half2_rn(pa[it].z, pa[it].w);
            *(uint2*)(sm + boff + (uint32_t)r * (A_STR * 2) + c4 * 8) =
                make_uint2(*(uint32_t*)&h01, *(uint32_t*)&h23);
        }
#pragma unroll
        for (int it = 0; it < B_IT; it++) {
            int u = tid + it * THREADS;
            int r = u / (BN / 8), c8 = u % (BN / 8);
            *(uint4*)(sm + boff + ASZ + (uint32_t)r * (B_STR * 2) + c8 * 16) = pb[it];
        }
    };

    auto compute = [&](int b) {
        uint32_t bA = aBase + (uint32_t)b * BUF;
        uint32_t bB = bA + ASZ;
#pragma unroll
        for (int ks = 0; ks < 2; ks++) {
            uint32_t ah[MF][4];
#pragma unroll
            for (int mf = 0; mf < MF; mf++) {
                int row = wm * WM + mf * 16 + (lane & 15);
                ldsm4(ah[mf], bA + (uint32_t)row * (A_STR * 2) + ks * 32 + ((lane >> 4) << 4));
            }
#pragma unroll
            for (int j = 0; j < NF / 2; j++) {
                int rB = ks * 16 + (lane & 15);
                int col = wn * WN + j * 16 + ((lane >> 4) << 3);
                uint32_t bh[4];
                ldsm4t(bh, bB + (uint32_t)rB * (B_STR * 2) + col * 2);
#pragma unroll
                for (int mf = 0; mf < MF; mf++) {
                    mma16816f(acc[mf][2 * j],     ah[mf], bh);
                    mma16816f(acc[mf][2 * j + 1], ah[mf], bh + 2);
                }
            }
        }
    };

    prefetch(0);
    store_smem(0);
    __syncthreads();
    for (int ic = 0; ic < NC; ic++) {
        if (ic + 1 < NC) prefetch((ic + 1) * BK);
        compute(ic & 1);
        if (ic + 1 < NC) {
            store_smem((ic + 1) & 1);
            __syncthreads();
        }
    }

    // ---- epilogue ----
    const int grp = lane >> 2, qd = lane & 3;
#pragma unroll
    for (int mf = 0; mf < MF; mf++) {
#pragma unroll
        for (int nf = 0; nf < NF; nf++) {
            int col = wn * WN + nf * 8 + qd * 2;
            float bv0 = __ldg(bias + col), bv1 = __ldg(bias + col + 1);
            int r0 = bm + wm * WM + mf * 16 + grp;
#pragma unroll
            for (int h = 0; h < 2; h++) {
                int r = r0 + h * 8;
                if (r < M) {
                    float v0 = acc[mf][nf][2 * h + 0] + bv0;
                    float v1 = acc[mf][nf][2 * h + 1] + bv1;
                    if (RELU) { v0 = fmaxf(v0, 0.f); v1 = fmaxf(v1, 0.f); }
                    *(float2*)(C + (size_t)r * NT + col) = make_float2(v0, v1);
                    if (DUAL)
                        *(__half2*)(H16 + (size_t)r * NT + col) = __floats2half2_rn(v0, v1);
                }
            }
        }
    }
}

// ---------------- edge index access ----------------
__device__ __forceinline__ int edge_at(const void* p, int is64, long long i) {
    return is64 ? (int)((const long long*)p)[i] : ((const int*)p)[i];
}

// init degrees + int64/int32 layout detect (g_nonzero monotonic, zero-init)
__global__ void k_init(const int* p, int n) {
    int i = blockIdx.x * blockDim.x + threadIdx.x;
    if (i < n) g_deg[i] = 1;
    if (i < 1024 && p[2 * i + 1] != 0) atomicOr(&g_nonzero, 1);
}
__global__ void k_count(const void* e, int E) {
    int i = blockIdx.x * blockDim.x + threadIdx.x;
    if (i >= E) return;
    int is64 = (g_nonzero == 0);
    atomicAdd(&g_deg[edge_at(e, is64, (long long)E + i)], 1);
}
__global__ void k_scan1(int n) {
    __shared__ int ws[32];
    int b = blockIdx.x, t = threadIdx.x;
    int i = b * 1024 + t;
    int v = (i < n) ? g_deg[i] : 0;
    if (i < n) g_dinv[i] = rsqrtf((float)v);     // fused dinv
    int lane = t & 31, wid = t >> 5;
    int x = v;
#pragma unroll
    for (int o = 1; o < 32; o <<= 1) { int y = __shfl_up_sync(0xffffffffu, x, o); if (lane >= o) x += y; }
    if (lane == 31) ws[wid] = x;
    __syncthreads();
    if (wid == 0) {
        int s = ws[lane];
#pragma unroll
        for (int o = 1; o < 32; o <<= 1) { int y = __shfl_up_sync(0xffffffffu, s, o); if (lane >= o) s += y; }
        ws[lane] = s;
    }
    __syncthreads();
    int off = wid ? ws[wid - 1] : 0;
    if (i < n) g_rowptr[i] = off + x - v;
    if (t == 1023) g_bsums[b] = ws[31];
}
__global__ void k_scan2(int nb) {
    __shared__ int ws[32];
    int t = threadIdx.x;
    int v = (t < nb) ? g_bsums[t] : 0;
    int lane = t & 31, wid = t >> 5;
    int x = v;
#pragma unroll
    for (int o = 1; o < 32; o <<= 1) { int y = __shfl_up_sync(0xffffffffu, x, o); if (lane >= o) x += y; }
    if (lane == 31) ws[wid] = x;
    __syncthreads();
    if (wid == 0) {
        int s = ws[lane];
#pragma unroll
        for (int o = 1; o < 32; o <<= 1) { int y = __shfl_up_sync(0xffffffffu, s, o); if (lane >= o) s += y; }
        ws[lane] = s;
    }
    __syncthreads();
    int off = wid ? ws[wid - 1] : 0;
    if (t < nb) g_bsums[t] = off + x - v;
}
__global__ void k_scan3(int n, int total) {
    int i = blockIdx.x * blockDim.x + threadIdx.x;
    if (i < n) {
        g_rowptr[i] += g_bsums[i >> 10];
        g_ctr[i] = g_rowptr[i];
    }
    if (i == 0) g_rowptr[n] = total;
}
__global__ void k_fill(const void* e, int E, int n) {
    int i = blockIdx.x * blockDim.x + threadIdx.x;
    if (i >= E + n) return;
    int is64 = (g_nonzero == 0);
    int s, d;
    if (i < E) { s = edge_at(e, is64, i); d = edge_at(e, is64, (long long)E + i); }
    else       { s = d = i - E; }
    int p = atomicAdd(&g_ctr[d], 1);
    float v = g_dinv[s] * g_dinv[d];
    g_edge[p] = make_int2(s, __float_as_int(v));
}

// -------- fp16 propagation: 1 warp/row, 4 edges in flight (LDG.128) ---------
template <bool LAST>
__global__ void k_prop16(const __half* __restrict__ hin, const float* __restrict__ h0,
                         __half* __restrict__ hout, float* __restrict__ fout, int n) {
    int w = (blockIdx.x * blockDim.x + threadIdx.x) >> 5;
    if (w >= n) return;
    int lane = threadIdx.x & 31;
    int g = lane >> 3, sl = lane & 7;      // 4 groups of 8 lanes
    int s = g_rowptr[w], e = g_rowptr[w + 1];
    float acc[8] = {};

#pragma unroll 2
    for (int i = s + g; i < e; i += 4) {
        int2 cv = __ldg(&g_edge[i]);
        float wv = __int_as_float(cv.y);
        const uint4* row = (const uint4*)(hin + (size_t)cv.x * OUTD);
        uint4 pk = __ldg(row + sl);
        float2 f0 = __half22float2(*(const __half2*)&pk.x);
        float2 f1 = __half22float2(*(const __half2*)&pk.y);
        float2 f2 = __half22float2(*(const __half2*)&pk.z);
        float2 f3 = __half22float2(*(const __half2*)&pk.w);
        acc[0] += wv * f0.x; acc[1] += wv * f0.y;
        acc[2] += wv * f1.x; acc[3] += wv * f1.y;
        acc[4] += wv * f2.x; acc[5] += wv * f2.y;
        acc[6] += wv * f3.x; acc[7] += wv * f3.y;
    }
#pragma unroll
    for (int j = 0; j < 8; j++) {
        acc[j] += __shfl_xor_sync(0xffffffffu, acc[j], 8);
        acc[j] += __shfl_xor_sync(0xffffffffu, acc[j], 16);
    }
    if (g == 0) {
        size_t o = (size_t)w * OUTD + sl * 8;
        float4 z0 = *(const float4*)(h0 + o);
        float4 z1 = *(const float4*)(h0 + o + 4);
        float r[8];
        r[0] = 0.9f * acc[0] + 0.1f * z0.x; r[1] = 0.9f * acc[1] + 0.1f * z0.y;
        r[2] = 0.9f * acc[2] + 0.1f * z0.z; r[3] = 0.9f * acc[3] + 0.1f * z0.w;
        r[4] = 0.9f * acc[4] + 0.1f * z1.x; r[5] = 0.9f * acc[5] + 0.1f * z1.y;
        r[6] = 0.9f * acc[6] + 0.1f * z1.z; r[7] = 0.9f * acc[7] + 0.1f * z1.w;
        if (LAST) {
            *(float4*)(fout + o)     = make_float4(r[0], r[1], r[2], r[3]);
            *(float4*)(fout + o + 4) = make_float4(r[4], r[5], r[6], r[7]);
        } else {
            uint4 pk;
            *(__half2*)&pk.x = __floats2half2_rn(r[0], r[1]);
            *(__half2*)&pk.y = __floats2half2_rn(r[2], r[3]);
            *(__half2*)&pk.z = __floats2half2_rn(r[4], r[5]);
            *(__half2*)&pk.w = __floats2half2_rn(r[6], r[7]);
            *(uint4*)(hout + (size_t)w * OUTD + sl * 8) = pk;
        }
    }
}

// ---------------- launch ----------------------------------------------------
extern "C" void kernel_launch(void* const* d_in, const int* in_sizes, int n_in,
                              void* d_out, int out_size) {
    const float* x  = (const float*)d_in[0];
    const void*  ei = d_in[1];
    const float* W1 = (const float*)d_in[2];
    const float* b1 = (const float*)d_in[3];
    const float* W2 = (const float*)d_in[4];
    const float* b2 = (const float*)d_in[5];
    float* out = (float*)d_out;

    int N = in_sizes[0] / IND;
    int E = in_sizes[1] / 2;

    void* p;
    cudaGetSymbolAddress(&p, g_h1);   float* h1 = (float*)p;
    cudaGetSymbolAddress(&p, g_h0);   float* h0 = (float*)p;
    cudaGetSymbolAddress(&p, g_h16a); __half* ha = (__half*)p;
    cudaGetSymbolAddress(&p, g_h16b); __half* hb = (__half*)p;
    cudaGetSymbolAddress(&p, g_w1f);  __half* w1f = (__half*)p;
    cudaGetSymbolAddress(&p, g_w2f);  __half* w2f = (__half*)p;

    int nb = (N + 1023) / 1024;
    int gm = (N + 127) / 128;
    int wtot = IND * HID + HID * OUTD;

    constexpr int SM1 = 2 * (128 * 40 * 2 + 32 * (HID + 8) * 2);   // 54272
    constexpr int SM2 = 2 * (128 * 40 * 2 + 32 * (OUTD + 8) * 2);  // 29696
    cudaFuncSetAttribute(gemm_fp16<HID, IND, 4, 4, 512, true, false>,
                         cudaFuncAttributeMaxDynamicSharedMemorySize, SM1);
    cudaFuncSetAttribute(gemm_fp16<OUTD, HID, 8, 1, 256, false, true>,
                         cudaFuncAttributeMaxDynamicSharedMemorySize, SM2);

    // Launch order keeps gemm1 at slot 4 (the ncu-captured launch).
    k_wconv<<<(wtot + 255) / 256, 256>>>(W1, W2);                       // 1
    k_init<<<(N + 255) / 256, 256>>>((const int*)ei, N);                // 2
    k_count<<<(E + 255) / 256, 256>>>(ei, E);                           // 3
    gemm_fp16<HID, IND, 4, 4, 512, true, false><<<gm, 512, SM1>>>(      // 4
        x, w1f, b1, h1, nullptr, N);
    k_scan1<<<nb, 1024>>>(N);                                           // 5
    k_scan2<<<1, 1024>>>(nb);                                           // 6
    k_scan3<<<nb, 1024>>>(N, E + N);                                    // 7
    gemm_fp16<OUTD, HID, 8, 1, 256, false, true><<<gm, 256, SM2>>>(     // 8
        h1, w2f, b2, h0, ha, N);
    k_fill<<<(E + N + 255) / 256, 256>>>(ei, E, N);                     // 9

    __half* bufs[2] = {ha, hb};
    int blocks = (N * 32 + 255) / 256;
    for (int it = 0; it < 10; it++) {
        const __half* hin = bufs[it & 1];
        if (it == 9) {
            k_prop16<true><<<blocks, 256>>>(hin, h0, nullptr, out, N);
        } else {
            k_prop16<false><<<blocks, 256>>>(hin, h0, bufs[(it + 1) & 1], nullptr, N);
        }
    }
}